// round 2
// baseline (speedup 1.0000x reference)
#include <cuda_runtime.h>
#include <cstdint>

// ---------------- problem constants ----------------
#define BB   2
#define L2C  1024
#define L1C  8192
#define L0C  65536
#define SC   (L2C + L1C + L0C)   // 74752
#define DC   256
#define CONVC 4

// ---------------- scratch (__device__ globals; no allocation allowed) ----------------
__device__ float g_E[(long)BB * SC * DC];          // embeddings, ~146 MB
__device__ float g_Wt0[2048 * 256];
__device__ float g_Wt1[2048 * 256];
__device__ float g_Wt2[1024 * 256];
__device__ float g_y0[BB * L1C * DC];              // conv0 out (B,8192,256)
__device__ float g_x1[BB * L1C * DC];              // substituted x1
__device__ float g_y1[BB * 1024 * DC];             // conv1 out (B,1024,256)
__device__ float g_x2[BB * L2C * DC];              // substituted x2
__device__ float g_xout[BB * 256 * DC];            // conv2 out (B,256,256)
__device__ int   g_srcrow1[BB * L1C];
__device__ int   g_srcrow2[BB * L2C];
__device__ int   g_outrow[BB * 256];

// ---------------- block-wide exclusive scan (256 threads) ----------------
__device__ __forceinline__ int exscan256(int v, int tid, int* sScan, int* total) {
    sScan[tid] = v;
    __syncthreads();
    #pragma unroll
    for (int off = 1; off < 256; off <<= 1) {
        int t = (tid >= off) ? sScan[tid - off] : 0;
        __syncthreads();
        sScan[tid] += t;
        __syncthreads();
    }
    int incl = sScan[tid];
    *total = sScan[255];
    __syncthreads();
    return incl - v;
}

// ---------------- index / mask precomputation (depends only on `value`) ----------------
__global__ void k_indices(const int* __restrict__ value) {
    __shared__ int sOrder[8192];
    __shared__ int sScan[256];
    __shared__ int sOut[256];
    int b = blockIdx.x, tid = threadIdx.x;
    const int* vb = value + (long)b * SC;

    // ---- substitution 1: targets = x1 (L1), sources = y0 rows (L0/8 = 8192) ----
    {
        int base = tid * 32, local = 0;
        unsigned mask = 0;
        #pragma unroll 8
        for (int i = 0; i < 32; i++) {
            int p = (vb[L2C + L1C + (base + i) * 8] != 0);
            mask |= (unsigned)p << i; local += p;
        }
        int tot; int ex = exscan256(local, tid, sScan, &tot);
        int rt = ex, rf = base - ex;
        for (int i = 0; i < 32; i++) {
            int j = base + i;
            if ((mask >> i) & 1u) sOrder[rt++] = j;
            else                  sOrder[tot + rf++] = j;
        }
        __syncthreads();
        local = 0; mask = 0;
        #pragma unroll 8
        for (int i = 0; i < 32; i++) {
            int p = (vb[L2C + base + i] == 2);
            mask |= (unsigned)p << i; local += p;
        }
        ex = exscan256(local, tid, sScan, &tot);
        int r = ex;
        for (int i = 0; i < 32; i++) {
            int j = base + i; int sr = -1;
            if ((mask >> i) & 1u) { sr = sOrder[min(r, 8191)]; r++; }
            g_srcrow1[b * L1C + j] = sr;
        }
        __syncthreads();
    }

    // ---- substitution 2: targets = x2 (L2), sources = y1 rows (L1/8 = 1024) ----
    {
        int base = tid * 4, local = 0;
        unsigned mask = 0;
        for (int i = 0; i < 4; i++) {
            int p = (vb[L2C + (base + i) * 8] != 0);
            mask |= (unsigned)p << i; local += p;
        }
        int tot; int ex = exscan256(local, tid, sScan, &tot);
        int rt = ex, rf = base - ex;
        for (int i = 0; i < 4; i++) {
            int j = base + i;
            if ((mask >> i) & 1u) sOrder[rt++] = j;
            else                  sOrder[tot + rf++] = j;
        }
        __syncthreads();
        local = 0; mask = 0;
        for (int i = 0; i < 4; i++) {
            int p = (vb[base + i] == 2);
            mask |= (unsigned)p << i; local += p;
        }
        ex = exscan256(local, tid, sScan, &tot);
        int r = ex;
        for (int i = 0; i < 4; i++) {
            int j = base + i; int sr = -1;
            if ((mask >> i) & 1u) { sr = sOrder[min(r, 1023)]; r++; }
            g_srcrow2[b * L2C + j] = sr;
        }
        __syncthreads();
    }

    // ---- final output gather mask ----
    {
        int* sM1 = sOrder;  // reuse: m1 over 1024 groups of v1
        for (int j = tid; j < 1024; j += 256) {
            int any = 0;
            for (int t = 0; t < 8; t++) any |= (vb[L2C + 8 * j + t] == 2);
            sM1[j] = any;
        }
        __syncthreads();
        int base = tid * 4, local = 0;
        unsigned mask = 0;
        for (int i = 0; i < 4; i++) {
            int p = (vb[base + i] == 2);
            mask |= (unsigned)p << i; local += p;
        }
        int tot; int ex = exscan256(local, tid, sScan, &tot);
        int r = ex, m2g = 0;
        for (int i = 0; i < 4; i++) {
            if ((mask >> i) & 1u) { m2g |= sM1[min(r, 1023)]; r++; }
        }
        int cnt; int ex2 = exscan256(m2g ? 1 : 0, tid, sScan, &cnt);
        (void)cnt;
        sOut[tid] = -1;
        __syncthreads();
        if (m2g) sOut[ex2] = tid;
        __syncthreads();
        g_outrow[b * 256 + tid] = sOut[tid];
    }
}

// ---------------- embedding ----------------
__global__ void k_embed(const int* __restrict__ value, const int* __restrict__ depth,
                        const int* __restrict__ position,
                        const float* __restrict__ emb_val, const float* __restrict__ emb_dep,
                        const float* __restrict__ emb_pos) {
    int s = blockIdx.x, b = blockIdx.y, d = threadIdx.x;
    long row = (long)b * SC + s;
    int v = value[row], dep = depth[row];
    const int* p = position + row * 3;
    int p0 = p[0], p1 = p[1], p2 = p[2];
    float e = emb_val[v * DC + d] + emb_dep[dep * DC + d]
            + emb_pos[(0 * 33 + p0) * DC + d]
            + emb_pos[(1 * 33 + p1) * DC + d]
            + emb_pos[(2 * 33 + p2) * DC + d];
    g_E[row * DC + d] = e;
}

// ---------------- weight transpose: Wt[(k*D+d)*256 + o] = W[(o*D+d)*sK + k] ----------------
__global__ void k_transpose(const float* __restrict__ W, float* __restrict__ Wt, int sK) {
    int idx = blockIdx.x * blockDim.x + threadIdx.x;
    int n = sK * DC * 256;
    if (idx >= n) return;
    int o = idx & 255;
    int kd = idx >> 8;
    int d = kd & 255;
    int k = kd >> 8;
    Wt[idx] = W[(o * DC + d) * sK + k];
}

// ---------------- SGEMM: C[M x 256] = A[M x K] @ Bt[K x 256] + bias ----------------
// BM=128, BN=64, BK=16, 256 threads, 8x4 micro-tile per thread.
template <int STAGE>
__global__ void __launch_bounds__(256) k_gemm(const float* __restrict__ bias) {
    constexpr int KK = (STAGE == 2) ? 1024 : 2048;
    constexpr int BM = 128, BN = 64, BK = 16;
    constexpr int ASTRIDE = 132;

    const float* A; const float* Bt; float* C;
    long sA, sC;
    if (STAGE == 0) { A = g_E + (long)(L2C + L1C) * DC; Bt = g_Wt0; C = g_y0;  sA = (long)SC * DC;  sC = (long)L1C * DC; }
    else if (STAGE == 1) { A = g_x1; Bt = g_Wt1; C = g_y1;  sA = (long)L1C * DC; sC = (long)1024 * DC; }
    else { A = g_x2; Bt = g_Wt2; C = g_xout; sA = (long)L2C * DC; sC = (long)256 * DC; }

    __shared__ float As[BK][ASTRIDE];
    __shared__ float Bs[BK][BN];

    int b = blockIdx.z;
    const float* Ab = A + (long)b * sA;
    float* Cb = C + (long)b * sC;
    int m0 = blockIdx.x * BM;
    int n0 = blockIdx.y * BN;
    int tid = threadIdx.x;
    int tx = tid & 15, ty = tid >> 4;

    float acc[8][4];
    #pragma unroll
    for (int i = 0; i < 8; i++)
        #pragma unroll
        for (int j = 0; j < 4; j++) acc[i][j] = 0.f;

    int bK = tid >> 4;            // 0..15
    int bN4 = (tid & 15) * 4;     // 0..60

    for (int k0 = 0; k0 < KK; k0 += BK) {
        // load A tile (2048 floats), transposed into As[k][m]
        #pragma unroll
        for (int l = 0; l < 2; l++) {
            int i = tid + l * 256;
            int m = i >> 2;
            int k4 = (i & 3) * 4;
            float4 v = *(const float4*)(Ab + (long)(m0 + m) * KK + k0 + k4);
            As[k4 + 0][m] = v.x;
            As[k4 + 1][m] = v.y;
            As[k4 + 2][m] = v.z;
            As[k4 + 3][m] = v.w;
        }
        // load B tile (16 x 64)
        {
            float4 v = *(const float4*)(Bt + (long)(k0 + bK) * 256 + n0 + bN4);
            *(float4*)&Bs[bK][bN4] = v;
        }
        __syncthreads();
        #pragma unroll
        for (int kk = 0; kk < BK; kk++) {
            float a[8], bb[4];
            #pragma unroll
            for (int i = 0; i < 8; i++) a[i] = As[kk][ty * 8 + i];
            #pragma unroll
            for (int j = 0; j < 4; j++) bb[j] = Bs[kk][tx * 4 + j];
            #pragma unroll
            for (int i = 0; i < 8; i++)
                #pragma unroll
                for (int j = 0; j < 4; j++)
                    acc[i][j] += a[i] * bb[j];
        }
        __syncthreads();
    }

    // epilogue with bias
    float4 bv = *(const float4*)(bias + n0 + tx * 4);
    #pragma unroll
    for (int i = 0; i < 8; i++) {
        int m = m0 + ty * 8 + i;
        float4 o;
        o.x = acc[i][0] + bv.x;
        o.y = acc[i][1] + bv.y;
        o.z = acc[i][2] + bv.z;
        o.w = acc[i][3] + bv.w;
        *(float4*)&Cb[(long)m * 256 + n0 + tx * 4] = o;
    }
}

// ---------------- substitution gathers ----------------
__global__ void k_gather_x1() {
    int l = blockIdx.x, b = blockIdx.y, d = threadIdx.x;
    int sr = g_srcrow1[b * L1C + l];
    float v = (sr >= 0) ? g_y0[((long)b * L1C + sr) * DC + d]
                        : g_E[((long)b * SC + L2C + l) * DC + d];
    g_x1[((long)b * L1C + l) * DC + d] = v;
}

__global__ void k_gather_x2() {
    int l = blockIdx.x, b = blockIdx.y, d = threadIdx.x;
    int sr = g_srcrow2[b * L2C + l];
    float v = (sr >= 0) ? g_y1[((long)b * 1024 + sr) * DC + d]
                        : g_E[((long)b * SC + l) * DC + d];
    g_x2[((long)b * L2C + l) * DC + d] = v;
}

// ---------------- final compaction + zero fill ----------------
__global__ void k_output(float* __restrict__ out) {
    int g = blockIdx.x, b = blockIdx.y, d = threadIdx.x;
    int sr = g_outrow[b * 256 + g];
    out[((long)b * 256 + g) * DC + d] = (sr >= 0) ? g_xout[((long)b * 256 + sr) * DC + d] : 0.f;
}

// ---------------- launch ----------------
extern "C" void kernel_launch(void* const* d_in, const int* in_sizes, int n_in,
                              void* d_out, int out_size) {
    (void)in_sizes; (void)n_in; (void)out_size;
    const int*   value    = (const int*)d_in[0];
    const int*   depth    = (const int*)d_in[1];
    const int*   position = (const int*)d_in[2];
    const float* emb_val  = (const float*)d_in[3];
    const float* emb_dep  = (const float*)d_in[4];
    const float* emb_pos  = (const float*)d_in[5];
    const float* W0 = (const float*)d_in[6];
    const float* b0 = (const float*)d_in[7];
    const float* W1 = (const float*)d_in[8];
    const float* b1 = (const float*)d_in[9];
    const float* W2 = (const float*)d_in[10];
    const float* b2 = (const float*)d_in[11];
    float* out = (float*)d_out;

    float* wt0; cudaGetSymbolAddress((void**)&wt0, g_Wt0);
    float* wt1; cudaGetSymbolAddress((void**)&wt1, g_Wt1);
    float* wt2; cudaGetSymbolAddress((void**)&wt2, g_Wt2);

    k_transpose<<<(8 * 256 * 256 + 255) / 256, 256>>>(W0, wt0, 8);
    k_transpose<<<(8 * 256 * 256 + 255) / 256, 256>>>(W1, wt1, 8);
    k_transpose<<<(4 * 256 * 256 + 255) / 256, 256>>>(W2, wt2, 4);
    k_indices<<<BB, 256>>>(value);
    k_embed<<<dim3(SC, BB), 256>>>(value, depth, position, emb_val, emb_dep, emb_pos);

    k_gemm<0><<<dim3(L1C / 128, 4, BB), 256>>>(b0);   // conv0: 8192x2048x256 per batch
    k_gather_x1<<<dim3(L1C, BB), 256>>>();
    k_gemm<1><<<dim3(1024 / 128, 4, BB), 256>>>(b1);  // conv1: 1024x2048x256 per batch
    k_gather_x2<<<dim3(L2C, BB), 256>>>();
    k_gemm<2><<<dim3(256 / 128, 4, BB), 256>>>(b2);   // conv2: 256x1024x256 per batch
    k_output<<<dim3(256, BB), 256>>>(out);
}

// round 4
// speedup vs baseline: 2.6926x; 2.6926x over previous
#include <cuda_runtime.h>
#include <cuda_bf16.h>
#include <cstdint>

// ---------------- problem constants ----------------
#define BB   2
#define L2C  1024
#define L1C  8192
#define L0C  65536
#define SC   (L2C + L1C + L0C)   // 74752
#define DC   256

// ---------------- scratch (__device__ globals) ----------------
__device__ __nv_bfloat16 g_Ehi[(long)BB * SC * DC];
__device__ __nv_bfloat16 g_Elo[(long)BB * SC * DC];
__device__ __nv_bfloat16 g_W0hi[256 * 2048], g_W0lo[256 * 2048];
__device__ __nv_bfloat16 g_W1hi[256 * 2048], g_W1lo[256 * 2048];
__device__ __nv_bfloat16 g_W2hi[256 * 1024], g_W2lo[256 * 1024];
__device__ float g_y0[(long)BB * L1C * DC];
__device__ __nv_bfloat16 g_x1hi[BB * L1C * DC], g_x1lo[BB * L1C * DC];
__device__ float g_y1[BB * 1024 * DC];
__device__ __nv_bfloat16 g_x2hi[BB * L2C * DC], g_x2lo[BB * L2C * DC];
__device__ float g_xout[BB * 256 * DC];
__device__ int g_srcrow1[BB * L1C];
__device__ int g_srcrow2[BB * L2C];
__device__ int g_outrow[BB * 256];

// ---------------- helpers ----------------
__device__ __forceinline__ uint32_t smem_u32(const void* p) {
    uint32_t a;
    asm("{ .reg .u64 t; cvta.to.shared.u64 t, %1; cvt.u32.u64 %0, t; }" : "=r"(a) : "l"(p));
    return a;
}

__device__ __forceinline__ void split2(float x, __nv_bfloat16& h, __nv_bfloat16& l) {
    h = __float2bfloat16(x);
    l = __float2bfloat16(x - __bfloat162float(h));
}

__device__ __forceinline__ void cpasync16(uint32_t saddr, const void* gaddr) {
    asm volatile("cp.async.cg.shared.global [%0], [%1], 16;" :: "r"(saddr), "l"(gaddr));
}

__device__ __forceinline__ void ldsm4(uint32_t* r, uint32_t a) {
    asm volatile("ldmatrix.sync.aligned.m8n8.x4.shared.b16 {%0,%1,%2,%3}, [%4];"
                 : "=r"(r[0]), "=r"(r[1]), "=r"(r[2]), "=r"(r[3]) : "r"(a));
}
__device__ __forceinline__ void ldsm2(uint32_t* r, uint32_t a) {
    asm volatile("ldmatrix.sync.aligned.m8n8.x2.shared.b16 {%0,%1}, [%2];"
                 : "=r"(r[0]), "=r"(r[1]) : "r"(a));
}

__device__ __forceinline__ void mma16816(float* d, const uint32_t* a, const uint32_t* b) {
    asm volatile(
        "mma.sync.aligned.m16n8k16.row.col.f32.bf16.bf16.f32 "
        "{%0,%1,%2,%3}, {%4,%5,%6,%7}, {%8,%9}, {%0,%1,%2,%3};"
        : "+f"(d[0]), "+f"(d[1]), "+f"(d[2]), "+f"(d[3])
        : "r"(a[0]), "r"(a[1]), "r"(a[2]), "r"(a[3]), "r"(b[0]), "r"(b[1]));
}

// ---------------- exclusive scan over 1024 threads ----------------
__device__ __forceinline__ int exscan1024(int v, int tid, int* sScan, int* total) {
    sScan[tid] = v;
    __syncthreads();
    #pragma unroll
    for (int off = 1; off < 1024; off <<= 1) {
        int t = (tid >= off) ? sScan[tid - off] : 0;
        __syncthreads();
        sScan[tid] += t;
        __syncthreads();
    }
    int incl = sScan[tid];
    *total = sScan[1023];
    __syncthreads();
    return incl - v;
}

// ---------------- index precomputation: grid (B, 3), 1024 threads ----------------
__global__ void __launch_bounds__(1024) k_indices(const int* __restrict__ value) {
    __shared__ int sOrder[8192];
    __shared__ int sScan[1024];
    int b = blockIdx.x, sec = blockIdx.y, tid = threadIdx.x;
    const int* vb = value + (long)b * SC;

    if (sec == 0) {
        int base = tid * 8, local = 0;
        unsigned mask = 0;
        #pragma unroll
        for (int i = 0; i < 8; i++) {
            int p = (vb[L2C + L1C + (base + i) * 8] != 0);
            mask |= (unsigned)p << i; local += p;
        }
        int tot; int ex = exscan1024(local, tid, sScan, &tot);
        int rt = ex, rf = base - ex;
        #pragma unroll
        for (int i = 0; i < 8; i++) {
            int j = base + i;
            if ((mask >> i) & 1u) sOrder[rt++] = j;
            else                  sOrder[tot + rf++] = j;
        }
        __syncthreads();
        local = 0; mask = 0;
        #pragma unroll
        for (int i = 0; i < 8; i++) {
            int p = (vb[L2C + base + i] == 2);
            mask |= (unsigned)p << i; local += p;
        }
        ex = exscan1024(local, tid, sScan, &tot);
        int r = ex;
        #pragma unroll
        for (int i = 0; i < 8; i++) {
            int j = base + i; int sr = -1;
            if ((mask >> i) & 1u) { sr = sOrder[min(r, 8191)]; r++; }
            g_srcrow1[b * L1C + j] = sr;
        }
    } else if (sec == 1) {
        int p = (vb[L2C + tid * 8] != 0);
        int tot; int ex = exscan1024(p, tid, sScan, &tot);
        if (p) sOrder[ex] = tid;
        else   sOrder[tot + tid - ex] = tid;
        __syncthreads();
        int q = (vb[tid] == 2);
        int ex2 = exscan1024(q, tid, sScan, &tot);
        g_srcrow2[b * L2C + tid] = q ? sOrder[min(ex2, 1023)] : -1;
    } else {
        int any = 0;
        #pragma unroll
        for (int t = 0; t < 8; t++) any |= (vb[L2C + tid * 8 + t] == 2);
        sOrder[tid] = any;
        __syncthreads();
        int p = (vb[tid] == 2);
        int tot; int ex = exscan1024(p, tid, sScan, &tot);
        int m2 = p ? sOrder[min(ex, 1023)] : 0;
        sOrder[2048 + tid] = m2;
        __syncthreads();
        int m2g = 0;
        if (tid < 256)
            m2g = sOrder[2048 + 4 * tid] | sOrder[2048 + 4 * tid + 1]
                | sOrder[2048 + 4 * tid + 2] | sOrder[2048 + 4 * tid + 3];
        int ex2 = exscan1024((tid < 256 && m2g) ? 1 : 0, tid, sScan, &tot);
        if (tid < 256) sOrder[4096 + tid] = -1;
        __syncthreads();
        if (tid < 256 && m2g) sOrder[4096 + ex2] = tid;
        __syncthreads();
        if (tid < 256) g_outrow[b * 256 + tid] = sOrder[4096 + tid];
    }
}

// ---------------- embedding -> hi/lo bf16 ----------------
__global__ void k_embed(const int* __restrict__ value, const int* __restrict__ depth,
                        const int* __restrict__ position,
                        const float* __restrict__ emb_val, const float* __restrict__ emb_dep,
                        const float* __restrict__ emb_pos) {
    int s = blockIdx.x, b = blockIdx.y, d = threadIdx.x;
    long row = (long)b * SC + s;
    int v = value[row], dep = depth[row];
    const int* p = position + row * 3;
    float e = emb_val[v * DC + d] + emb_dep[dep * DC + d]
            + emb_pos[(0 * 33 + p[0]) * DC + d]
            + emb_pos[(1 * 33 + p[1]) * DC + d]
            + emb_pos[(2 * 33 + p[2]) * DC + d];
    __nv_bfloat16 h, l; split2(e, h, l);
    g_Ehi[row * DC + d] = h;
    g_Elo[row * DC + d] = l;
}

// ---------------- weight split: Whi[o][t*256+d] = hi(W[o][d][t]) ----------------
__global__ void k_wsplit(const float* __restrict__ W, __nv_bfloat16* __restrict__ Whi,
                         __nv_bfloat16* __restrict__ Wlo, int sK) {
    int idx = blockIdx.x * blockDim.x + threadIdx.x;
    int n = 256 * sK * 256;
    if (idx >= n) return;
    int d = idx & 255;
    int rem = idx >> 8;
    int t = rem % sK;
    int o = rem / sK;
    float w = W[(o * 256 + d) * sK + t];
    __nv_bfloat16 h, l; split2(w, h, l);
    int out = o * (sK * 256) + t * 256 + d;
    Whi[out] = h; Wlo[out] = l;
}

// ---------------- split-bf16 GEMM via mma.sync (portable HMMA path) ----------------
// C[M x 256] = (Ah+Al)[M x KK] @ (Bh+Bl)^T + bias, fp32 accumulate.
// CTA: 256 threads / 8 warps (2 x 4 warp grid). BK=64 bf16 (128B rows, SW128).
// 3-stage cp.async pipeline.
template <int BM, int BN, int KK>
__global__ void __launch_bounds__(256) k_gemm(
    const __nv_bfloat16* __restrict__ Ahi, const __nv_bfloat16* __restrict__ Alo, long strideA,
    const __nv_bfloat16* __restrict__ Bhi, const __nv_bfloat16* __restrict__ Blo,
    const float* __restrict__ bias, float* __restrict__ C, long strideC)
{
    constexpr int NC = KK / 64;
    constexpr int ABYTES = BM * 128;
    constexpr int BBYTES = BN * 128;
    constexpr int STAGE = 2 * ABYTES + 2 * BBYTES;
    constexpr int WM = BM / 2, WN = BN / 4;
    constexpr int MT = WM / 16, NTL = WN / 8;
    constexpr int TOTROWS = 2 * BM + 2 * BN;

    extern __shared__ __align__(1024) char smem[];
    uint32_t sb = smem_u32(smem);

    int tid = threadIdx.x;
    int lane = tid & 31, wid = tid >> 5;
    int wm0 = (wid >> 2) * WM;
    int wn0 = (wid & 3) * WN;
    int m0 = blockIdx.x * BM;
    int n0 = blockIdx.y * BN;
    int b = blockIdx.z;

    const __nv_bfloat16* Ah = Ahi + (long)b * strideA;
    const __nv_bfloat16* Al = Alo + (long)b * strideA;
    float* Cb = C + (long)b * strideC;

    float acc[MT][NTL][4];
    #pragma unroll
    for (int i = 0; i < MT; i++)
        #pragma unroll
        for (int j = 0; j < NTL; j++)
            #pragma unroll
            for (int k = 0; k < 4; k++) acc[i][j][k] = 0.f;

    auto load_chunk = [&](int c) {
        uint32_t st = sb + (uint32_t)((c % 3) * STAGE);
        long k0 = (long)c * 64;
        #pragma unroll
        for (int i = tid; i < TOTROWS * 8; i += 256) {
            int r = i >> 3, seg = i & 7;
            const __nv_bfloat16* g;
            uint32_t base;
            if (r < BM)               { g = Ah + (long)(m0 + r) * KK;            base = st; }
            else if (r < 2 * BM)      { int rr = r - BM;     g = Al + (long)(m0 + rr) * KK;  base = st + ABYTES;              r = rr; }
            else if (r < 2 * BM + BN) { int rr = r - 2 * BM; g = Bhi + (long)(n0 + rr) * KK; base = st + 2 * ABYTES;          r = rr; }
            else                      { int rr = r - 2 * BM - BN; g = Blo + (long)(n0 + rr) * KK; base = st + 2 * ABYTES + BBYTES; r = rr; }
            uint32_t off = (uint32_t)(r * 128 + seg * 16);
            uint32_t dst = base + (off ^ (uint32_t)((r & 7) << 4));
            cpasync16(dst, g + k0 + seg * 8);
        }
        asm volatile("cp.async.commit_group;" ::: "memory");
    };

    // prologue: stages 0 and 1
    load_chunk(0);
    load_chunk(1);

    const uint32_t xorm = (uint32_t)((lane & 7) << 4);
    const uint32_t arow = (uint32_t)(lane & 15);
    const uint32_t akhi = (uint32_t)(lane & 16);          // +16B for k-high half
    const uint32_t brow = (uint32_t)(lane & 7);
    const uint32_t bkhi = (uint32_t)((lane & 8) << 1);    // +16B for k-high half

    for (int c = 0; c < NC; ++c) {
        if (c + 1 < NC) asm volatile("cp.async.wait_group 1;" ::: "memory");
        else            asm volatile("cp.async.wait_group 0;" ::: "memory");
        __syncthreads();
        if (c + 2 < NC) load_chunk(c + 2);

        uint32_t st = sb + (uint32_t)((c % 3) * STAGE);
        #pragma unroll
        for (int ks = 0; ks < 4; ks++) {
            uint32_t a[2][MT][4], bf[2][NTL][2];
            #pragma unroll
            for (int mi = 0; mi < MT; mi++) {
                uint32_t off = (uint32_t)((wm0 + mi * 16) * 128) + arow * 128 + (uint32_t)(ks * 32) + akhi;
                ldsm4(a[0][mi], st + (off ^ xorm));
                ldsm4(a[1][mi], st + ABYTES + (off ^ xorm));
            }
            #pragma unroll
            for (int ni = 0; ni < NTL; ni++) {
                uint32_t off = (uint32_t)((wn0 + ni * 8) * 128) + brow * 128 + (uint32_t)(ks * 32) + bkhi;
                ldsm2(bf[0][ni], st + 2 * ABYTES + (off ^ xorm));
                ldsm2(bf[1][ni], st + 2 * ABYTES + BBYTES + (off ^ xorm));
            }
            #pragma unroll
            for (int mi = 0; mi < MT; mi++)
                #pragma unroll
                for (int ni = 0; ni < NTL; ni++) {
                    mma16816(acc[mi][ni], a[0][mi], bf[0][ni]);  // hi*hi
                    mma16816(acc[mi][ni], a[0][mi], bf[1][ni]);  // hi*lo
                    mma16816(acc[mi][ni], a[1][mi], bf[0][ni]);  // lo*hi
                }
        }
        __syncthreads();
    }

    // epilogue: direct fp32 stores with bias
    int g4 = lane >> 2, t4 = lane & 3;
    #pragma unroll
    for (int mi = 0; mi < MT; mi++) {
        #pragma unroll
        for (int ni = 0; ni < NTL; ni++) {
            int m = m0 + wm0 + mi * 16 + g4;
            int col = n0 + wn0 + ni * 8 + t4 * 2;
            float bx = bias[col], by = bias[col + 1];
            float2 v0 = make_float2(acc[mi][ni][0] + bx, acc[mi][ni][1] + by);
            float2 v1 = make_float2(acc[mi][ni][2] + bx, acc[mi][ni][3] + by);
            *(float2*)&Cb[(long)m * 256 + col] = v0;
            *(float2*)&Cb[(long)(m + 8) * 256 + col] = v1;
        }
    }
}

// ---------------- substitution gathers -> hi/lo bf16 ----------------
__global__ void k_gather_x1() {
    int l = blockIdx.x, b = blockIdx.y, d = threadIdx.x;
    int sr = g_srcrow1[b * L1C + l];
    long dst = ((long)b * L1C + l) * DC + d;
    if (sr >= 0) {
        float v = g_y0[((long)b * L1C + sr) * DC + d];
        __nv_bfloat16 h, lo; split2(v, h, lo);
        g_x1hi[dst] = h; g_x1lo[dst] = lo;
    } else {
        long src = ((long)b * SC + L2C + l) * DC + d;
        g_x1hi[dst] = g_Ehi[src]; g_x1lo[dst] = g_Elo[src];
    }
}

__global__ void k_gather_x2() {
    int l = blockIdx.x, b = blockIdx.y, d = threadIdx.x;
    int sr = g_srcrow2[b * L2C + l];
    long dst = ((long)b * L2C + l) * DC + d;
    if (sr >= 0) {
        float v = g_y1[((long)b * 1024 + sr) * DC + d];
        __nv_bfloat16 h, lo; split2(v, h, lo);
        g_x2hi[dst] = h; g_x2lo[dst] = lo;
    } else {
        long src = ((long)b * SC + l) * DC + d;
        g_x2hi[dst] = g_Ehi[src]; g_x2lo[dst] = g_Elo[src];
    }
}

// ---------------- final compaction + zero fill ----------------
__global__ void k_output(float* __restrict__ out) {
    int g = blockIdx.x, b = blockIdx.y, d = threadIdx.x;
    int sr = g_outrow[b * 256 + g];
    out[((long)b * 256 + g) * DC + d] = (sr >= 0) ? g_xout[((long)b * 256 + sr) * DC + d] : 0.f;
}

// ---------------- launch ----------------
extern "C" void kernel_launch(void* const* d_in, const int* in_sizes, int n_in,
                              void* d_out, int out_size) {
    (void)in_sizes; (void)n_in; (void)out_size;
    const int*   value    = (const int*)d_in[0];
    const int*   depth    = (const int*)d_in[1];
    const int*   position = (const int*)d_in[2];
    const float* emb_val  = (const float*)d_in[3];
    const float* emb_dep  = (const float*)d_in[4];
    const float* emb_pos  = (const float*)d_in[5];
    const float* W0 = (const float*)d_in[6];
    const float* b0 = (const float*)d_in[7];
    const float* W1 = (const float*)d_in[8];
    const float* b1 = (const float*)d_in[9];
    const float* W2 = (const float*)d_in[10];
    const float* b2 = (const float*)d_in[11];
    float* out = (float*)d_out;

    __nv_bfloat16 *w0h, *w0l, *w1h, *w1l, *w2h, *w2l, *ehi, *elo;
    __nv_bfloat16 *x1h, *x1l, *x2h, *x2l;
    float *y0, *y1, *xo;
    cudaGetSymbolAddress((void**)&w0h, g_W0hi); cudaGetSymbolAddress((void**)&w0l, g_W0lo);
    cudaGetSymbolAddress((void**)&w1h, g_W1hi); cudaGetSymbolAddress((void**)&w1l, g_W1lo);
    cudaGetSymbolAddress((void**)&w2h, g_W2hi); cudaGetSymbolAddress((void**)&w2l, g_W2lo);
    cudaGetSymbolAddress((void**)&ehi, g_Ehi);  cudaGetSymbolAddress((void**)&elo, g_Elo);
    cudaGetSymbolAddress((void**)&x1h, g_x1hi); cudaGetSymbolAddress((void**)&x1l, g_x1lo);
    cudaGetSymbolAddress((void**)&x2h, g_x2hi); cudaGetSymbolAddress((void**)&x2l, g_x2lo);
    cudaGetSymbolAddress((void**)&y0, g_y0);    cudaGetSymbolAddress((void**)&y1, g_y1);
    cudaGetSymbolAddress((void**)&xo, g_xout);

    const int SMEM0 = 3 * (2 * 128 * 128 + 2 * 128 * 128);  // 196608
    const int SMEM1 = 3 * (2 * 64 * 128 + 2 * 64 * 128);    // 98304
    cudaFuncSetAttribute(k_gemm<128, 128, 2048>, cudaFuncAttributeMaxDynamicSharedMemorySize, SMEM0);
    cudaFuncSetAttribute(k_gemm<64, 64, 2048>,   cudaFuncAttributeMaxDynamicSharedMemorySize, SMEM1);
    cudaFuncSetAttribute(k_gemm<64, 64, 1024>,   cudaFuncAttributeMaxDynamicSharedMemorySize, SMEM1);

    k_wsplit<<<(256 * 8 * 256 + 255) / 256, 256>>>(W0, w0h, w0l, 8);
    k_wsplit<<<(256 * 8 * 256 + 255) / 256, 256>>>(W1, w1h, w1l, 8);
    k_wsplit<<<(256 * 4 * 256 + 255) / 256, 256>>>(W2, w2h, w2l, 4);
    k_indices<<<dim3(BB, 3), 1024>>>(value);
    k_embed<<<dim3(SC, BB), 256>>>(value, depth, position, emb_val, emb_dep, emb_pos);

    // GEMM0: 8192 x 2048 x 256 per batch
    k_gemm<128, 128, 2048><<<dim3(64, 2, BB), 256, SMEM0>>>(
        ehi + (long)(L2C + L1C) * DC, elo + (long)(L2C + L1C) * DC, (long)SC * DC,
        w0h, w0l, b0, y0, (long)L1C * DC);
    k_gather_x1<<<dim3(L1C, BB), 256>>>();
    // GEMM1: 1024 x 2048 x 256 per batch
    k_gemm<64, 64, 2048><<<dim3(16, 4, BB), 256, SMEM1>>>(
        x1h, x1l, (long)L1C * DC, w1h, w1l, b1, y1, (long)1024 * DC);
    k_gather_x2<<<dim3(L2C, BB), 256>>>();
    // GEMM2: 256 x 1024 x 256 per batch
    k_gemm<64, 64, 1024><<<dim3(4, 4, BB), 256, SMEM1>>>(
        x2h, x2l, (long)L2C * DC, w2h, w2l, b2, xo, (long)256 * DC);
    k_output<<<dim3(256, BB), 256>>>(out);
}

// round 5
// speedup vs baseline: 2.8077x; 1.0427x over previous
#include <cuda_runtime.h>
#include <cuda_bf16.h>
#include <cstdint>

// ---------------- problem constants ----------------
#define BB   2
#define L2C  1024
#define L1C  8192
#define L0C  65536
#define SC   (L2C + L1C + L0C)   // 74752
#define DC   256

// ---------------- scratch (__device__ globals) ----------------
__device__ __nv_bfloat16 g_Ehi[(long)BB * SC * DC];
__device__ __nv_bfloat16 g_Elo[(long)BB * SC * DC];
__device__ __nv_bfloat16 g_W0hi[256 * 2048], g_W0lo[256 * 2048];
__device__ __nv_bfloat16 g_W1hi[256 * 2048], g_W1lo[256 * 2048];
__device__ __nv_bfloat16 g_W2hi[256 * 1024], g_W2lo[256 * 1024];
__device__ float g_y0[(long)BB * L1C * DC];
__device__ __nv_bfloat16 g_x1hi[BB * L1C * DC], g_x1lo[BB * L1C * DC];
__device__ float g_y1[BB * 1024 * DC];
__device__ __nv_bfloat16 g_x2hi[BB * L2C * DC], g_x2lo[BB * L2C * DC];
__device__ float g_xout[BB * 256 * DC];
__device__ int g_srcrow1[BB * L1C];
__device__ int g_srcrow2[BB * L2C];
__device__ int g_outrow[BB * 256];

// ---------------- helpers ----------------
__device__ __forceinline__ uint32_t smem_u32(const void* p) {
    uint32_t a;
    asm("{ .reg .u64 t; cvta.to.shared.u64 t, %1; cvt.u32.u64 %0, t; }" : "=r"(a) : "l"(p));
    return a;
}

__device__ __forceinline__ void split2(float x, __nv_bfloat16& h, __nv_bfloat16& l) {
    h = __float2bfloat16(x);
    l = __float2bfloat16(x - __bfloat162float(h));
}

__device__ __forceinline__ void cpasync16(uint32_t saddr, const void* gaddr) {
    asm volatile("cp.async.cg.shared.global [%0], [%1], 16;" :: "r"(saddr), "l"(gaddr));
}

__device__ __forceinline__ void ldsm4(uint32_t* r, uint32_t a) {
    asm volatile("ldmatrix.sync.aligned.m8n8.x4.shared.b16 {%0,%1,%2,%3}, [%4];"
                 : "=r"(r[0]), "=r"(r[1]), "=r"(r[2]), "=r"(r[3]) : "r"(a));
}

__device__ __forceinline__ void mma16816(float* d, const uint32_t* a, const uint32_t* b) {
    asm volatile(
        "mma.sync.aligned.m16n8k16.row.col.f32.bf16.bf16.f32 "
        "{%0,%1,%2,%3}, {%4,%5,%6,%7}, {%8,%9}, {%0,%1,%2,%3};"
        : "+f"(d[0]), "+f"(d[1]), "+f"(d[2]), "+f"(d[3])
        : "r"(a[0]), "r"(a[1]), "r"(a[2]), "r"(a[3]), "r"(b[0]), "r"(b[1]));
}

// ---------------- warp-shuffle exclusive scan over 1024 threads ----------------
__device__ __forceinline__ int exscan1024(int v, int tid, int* sW, int* total) {
    int lane = tid & 31, w = tid >> 5;
    int x = v;
    #pragma unroll
    for (int o = 1; o < 32; o <<= 1) {
        int t = __shfl_up_sync(0xFFFFFFFFu, x, o);
        if (lane >= o) x += t;
    }
    if (lane == 31) sW[w] = x;
    __syncthreads();
    if (tid < 32) {
        int y = sW[lane];
        #pragma unroll
        for (int o = 1; o < 32; o <<= 1) {
            int t = __shfl_up_sync(0xFFFFFFFFu, y, o);
            if (lane >= o) y += t;
        }
        sW[lane] = y;
    }
    __syncthreads();
    int off = (w == 0) ? 0 : sW[w - 1];
    int tot = sW[31];
    __syncthreads();           // sW reusable by next call
    *total = tot;
    return off + x - v;
}

// ---------------- index precomputation: grid (B, 3), 1024 threads ----------------
__global__ void __launch_bounds__(1024) k_indices(const int* __restrict__ value) {
    __shared__ int sOrder[8192];
    __shared__ int sScan[32];
    int b = blockIdx.x, sec = blockIdx.y, tid = threadIdx.x;
    const int* vb = value + (long)b * SC;

    if (sec == 0) {
        int base = tid * 8, local = 0;
        unsigned mask = 0;
        #pragma unroll
        for (int i = 0; i < 8; i++) {
            int p = (vb[L2C + L1C + (base + i) * 8] != 0);
            mask |= (unsigned)p << i; local += p;
        }
        int tot; int ex = exscan1024(local, tid, sScan, &tot);
        int rt = ex, rf = base - ex;
        #pragma unroll
        for (int i = 0; i < 8; i++) {
            int j = base + i;
            if ((mask >> i) & 1u) sOrder[rt++] = j;
            else                  sOrder[tot + rf++] = j;
        }
        __syncthreads();
        local = 0; mask = 0;
        #pragma unroll
        for (int i = 0; i < 8; i++) {
            int p = (vb[L2C + base + i] == 2);
            mask |= (unsigned)p << i; local += p;
        }
        ex = exscan1024(local, tid, sScan, &tot);
        int r = ex;
        #pragma unroll
        for (int i = 0; i < 8; i++) {
            int j = base + i; int sr = -1;
            if ((mask >> i) & 1u) { sr = sOrder[min(r, 8191)]; r++; }
            g_srcrow1[b * L1C + j] = sr;
        }
    } else if (sec == 1) {
        int p = (vb[L2C + tid * 8] != 0);
        int tot; int ex = exscan1024(p, tid, sScan, &tot);
        if (p) sOrder[ex] = tid;
        else   sOrder[tot + tid - ex] = tid;
        __syncthreads();
        int q = (vb[tid] == 2);
        int ex2 = exscan1024(q, tid, sScan, &tot);
        g_srcrow2[b * L2C + tid] = q ? sOrder[min(ex2, 1023)] : -1;
    } else {
        int any = 0;
        #pragma unroll
        for (int t = 0; t < 8; t++) any |= (vb[L2C + tid * 8 + t] == 2);
        sOrder[tid] = any;
        __syncthreads();
        int p = (vb[tid] == 2);
        int tot; int ex = exscan1024(p, tid, sScan, &tot);
        int m2 = p ? sOrder[min(ex, 1023)] : 0;
        sOrder[2048 + tid] = m2;
        __syncthreads();
        int m2g = 0;
        if (tid < 256)
            m2g = sOrder[2048 + 4 * tid] | sOrder[2048 + 4 * tid + 1]
                | sOrder[2048 + 4 * tid + 2] | sOrder[2048 + 4 * tid + 3];
        int ex2 = exscan1024((tid < 256 && m2g) ? 1 : 0, tid, sScan, &tot);
        if (tid < 256) sOrder[4096 + tid] = -1;
        __syncthreads();
        if (tid < 256 && m2g) sOrder[4096 + ex2] = tid;
        __syncthreads();
        if (tid < 256) g_outrow[b * 256 + tid] = sOrder[4096 + tid];
    }
}

// ---------------- embedding -> hi/lo bf16 ----------------
__global__ void k_embed(const int* __restrict__ value, const int* __restrict__ depth,
                        const int* __restrict__ position,
                        const float* __restrict__ emb_val, const float* __restrict__ emb_dep,
                        const float* __restrict__ emb_pos) {
    int s = blockIdx.x, b = blockIdx.y, d = threadIdx.x;
    long row = (long)b * SC + s;
    int v = value[row], dep = depth[row];
    const int* p = position + row * 3;
    float e = emb_val[v * DC + d] + emb_dep[dep * DC + d]
            + emb_pos[(0 * 33 + p[0]) * DC + d]
            + emb_pos[(1 * 33 + p[1]) * DC + d]
            + emb_pos[(2 * 33 + p[2]) * DC + d];
    __nv_bfloat16 h, l; split2(e, h, l);
    g_Ehi[row * DC + d] = h;
    g_Elo[row * DC + d] = l;
}

// ---------------- weight split ----------------
__global__ void k_wsplit(const float* __restrict__ W, __nv_bfloat16* __restrict__ Whi,
                         __nv_bfloat16* __restrict__ Wlo, int sK) {
    int idx = blockIdx.x * blockDim.x + threadIdx.x;
    int n = 256 * sK * 256;
    if (idx >= n) return;
    int d = idx & 255;
    int rem = idx >> 8;
    int t = rem % sK;
    int o = rem / sK;
    float w = W[(o * 256 + d) * sK + t];
    __nv_bfloat16 h, l; split2(w, h, l);
    int out = o * (sK * 256) + t * 256 + d;
    Whi[out] = h; Wlo[out] = l;
}

// ---------------- split-bf16 GEMM via mma.sync ----------------
// C[M x 256] = (Ah+Al)[M x KK] @ (Bh+Bl)^T + bias, fp32 accumulate.
// 256 threads / 8 warps in 2x4 grid. BK=64 bf16 (128B SW128 rows).
// STAGES-buffer cp.async pipeline (2 in-flight).
template <int BM, int BN, int KK, int STAGES>
__global__ void __launch_bounds__(256, 1) k_gemm(
    const __nv_bfloat16* __restrict__ Ahi, const __nv_bfloat16* __restrict__ Alo, long strideA,
    const __nv_bfloat16* __restrict__ Bhi, const __nv_bfloat16* __restrict__ Blo,
    const float* __restrict__ bias, float* __restrict__ C, long strideC)
{
    constexpr int NC = KK / 64;
    constexpr int ABYTES = BM * 128;
    constexpr int BBYTES = BN * 128;
    constexpr int STAGE = 2 * ABYTES + 2 * BBYTES;
    constexpr int WM = BM / 2, WN = BN / 4;
    constexpr int MT = WM / 16, NP = WN / 16;   // NP pairs of n8-tiles
    constexpr int TOTROWS = 2 * BM + 2 * BN;

    extern __shared__ __align__(1024) char smem[];
    uint32_t sb = smem_u32(smem);

    int tid = threadIdx.x;
    int lane = tid & 31, wid = tid >> 5;
    int wm0 = (wid >> 2) * WM;
    int wn0 = (wid & 3) * WN;
    int m0 = blockIdx.x * BM;
    int n0 = blockIdx.y * BN;
    int b = blockIdx.z;

    const __nv_bfloat16* Ah = Ahi + (long)b * strideA;
    const __nv_bfloat16* Al = Alo + (long)b * strideA;
    float* Cb = C + (long)b * strideC;

    float acc[MT][2 * NP][4];
    #pragma unroll
    for (int i = 0; i < MT; i++)
        #pragma unroll
        for (int j = 0; j < 2 * NP; j++)
            #pragma unroll
            for (int k = 0; k < 4; k++) acc[i][j][k] = 0.f;

    auto load_chunk = [&](int c) {
        uint32_t st = sb + (uint32_t)((c % STAGES) * STAGE);
        long k0 = (long)c * 64;
        #pragma unroll
        for (int i = tid; i < TOTROWS * 8; i += 256) {
            int r = i >> 3, seg = i & 7;
            const __nv_bfloat16* g;
            uint32_t base;
            if (r < BM)               { g = Ah + (long)(m0 + r) * KK;                 base = st; }
            else if (r < 2 * BM)      { int rr = r - BM;      g = Al + (long)(m0 + rr) * KK;  base = st + ABYTES;               r = rr; }
            else if (r < 2 * BM + BN) { int rr = r - 2 * BM;  g = Bhi + (long)(n0 + rr) * KK; base = st + 2 * ABYTES;           r = rr; }
            else                      { int rr = r - 2 * BM - BN; g = Blo + (long)(n0 + rr) * KK; base = st + 2 * ABYTES + BBYTES; r = rr; }
            uint32_t off = (uint32_t)(r * 128 + seg * 16);
            uint32_t dst = base + (off ^ (uint32_t)((r & 7) << 4));
            cpasync16(dst, g + k0 + seg * 8);
        }
        asm volatile("cp.async.commit_group;" ::: "memory");
    };

    load_chunk(0);
    load_chunk(1);

    const uint32_t xorm = (uint32_t)((lane & 7) << 4);
    // A ldsm4: rows m..m+15 (lanes 0-15), k-half selected by lane bit 4
    const uint32_t a_lrow = (uint32_t)(lane & 15);
    const uint32_t a_khalf = (uint32_t)(lane & 16);
    // B ldsm4 (pair of n8 tiles): row = (lane&7) | ((lane&16)>>1), k-half = (lane&8)<<1
    const uint32_t b_lrow = (uint32_t)((lane & 7) | ((lane & 16) >> 1));
    const uint32_t b_khalf = (uint32_t)((lane & 8) << 1);

    for (int c = 0; c < NC; ++c) {
        if (c + 1 < NC) asm volatile("cp.async.wait_group 1;" ::: "memory");
        else            asm volatile("cp.async.wait_group 0;" ::: "memory");
        __syncthreads();

        uint32_t st = sb + (uint32_t)((c % STAGES) * STAGE);
        #pragma unroll
        for (int ks = 0; ks < 4; ks++) {
            uint32_t a[2][MT][4], bf[2][NP][4];
            #pragma unroll
            for (int mi = 0; mi < MT; mi++) {
                uint32_t off = (uint32_t)((wm0 + mi * 16 + a_lrow) * 128) + (uint32_t)(ks * 32) + a_khalf;
                ldsm4(a[0][mi], st + (off ^ xorm));
                ldsm4(a[1][mi], st + ABYTES + (off ^ xorm));
            }
            #pragma unroll
            for (int pi = 0; pi < NP; pi++) {
                uint32_t off = (uint32_t)((wn0 + pi * 16 + b_lrow) * 128) + (uint32_t)(ks * 32) + b_khalf;
                ldsm4(bf[0][pi], st + 2 * ABYTES + (off ^ xorm));
                ldsm4(bf[1][pi], st + 2 * ABYTES + BBYTES + (off ^ xorm));
            }
            #pragma unroll
            for (int mi = 0; mi < MT; mi++)
                #pragma unroll
                for (int pi = 0; pi < NP; pi++) {
                    mma16816(acc[mi][2 * pi],     a[0][mi], &bf[0][pi][0]);   // hi*hi n-lo
                    mma16816(acc[mi][2 * pi + 1], a[0][mi], &bf[0][pi][2]);   // hi*hi n-hi
                    mma16816(acc[mi][2 * pi],     a[0][mi], &bf[1][pi][0]);   // hi*lo
                    mma16816(acc[mi][2 * pi + 1], a[0][mi], &bf[1][pi][2]);
                    mma16816(acc[mi][2 * pi],     a[1][mi], &bf[0][pi][0]);   // lo*hi
                    mma16816(acc[mi][2 * pi + 1], a[1][mi], &bf[0][pi][2]);
                }
        }
        __syncthreads();
        if (c + 2 < NC) load_chunk(c + 2);
    }

    // epilogue
    int g4 = lane >> 2, t4 = lane & 3;
    #pragma unroll
    for (int mi = 0; mi < MT; mi++) {
        #pragma unroll
        for (int ni = 0; ni < 2 * NP; ni++) {
            int m = m0 + wm0 + mi * 16 + g4;
            int col = n0 + wn0 + ni * 8 + t4 * 2;
            float bx = bias[col], by = bias[col + 1];
            float2 v0 = make_float2(acc[mi][ni][0] + bx, acc[mi][ni][1] + by);
            float2 v1 = make_float2(acc[mi][ni][2] + bx, acc[mi][ni][3] + by);
            *(float2*)&Cb[(long)m * 256 + col] = v0;
            *(float2*)&Cb[(long)(m + 8) * 256 + col] = v1;
        }
    }
}

// ---------------- substitution gathers -> hi/lo bf16 ----------------
__global__ void k_gather_x1() {
    int l = blockIdx.x, b = blockIdx.y, d = threadIdx.x;
    int sr = g_srcrow1[b * L1C + l];
    long dst = ((long)b * L1C + l) * DC + d;
    if (sr >= 0) {
        float v = g_y0[((long)b * L1C + sr) * DC + d];
        __nv_bfloat16 h, lo; split2(v, h, lo);
        g_x1hi[dst] = h; g_x1lo[dst] = lo;
    } else {
        long src = ((long)b * SC + L2C + l) * DC + d;
        g_x1hi[dst] = g_Ehi[src]; g_x1lo[dst] = g_Elo[src];
    }
}

__global__ void k_gather_x2() {
    int l = blockIdx.x, b = blockIdx.y, d = threadIdx.x;
    int sr = g_srcrow2[b * L2C + l];
    long dst = ((long)b * L2C + l) * DC + d;
    if (sr >= 0) {
        float v = g_y1[((long)b * 1024 + sr) * DC + d];
        __nv_bfloat16 h, lo; split2(v, h, lo);
        g_x2hi[dst] = h; g_x2lo[dst] = lo;
    } else {
        long src = ((long)b * SC + l) * DC + d;
        g_x2hi[dst] = g_Ehi[src]; g_x2lo[dst] = g_Elo[src];
    }
}

// ---------------- final compaction + zero fill ----------------
__global__ void k_output(float* __restrict__ out) {
    int g = blockIdx.x, b = blockIdx.y, d = threadIdx.x;
    int sr = g_outrow[b * 256 + g];
    out[((long)b * 256 + g) * DC + d] = (sr >= 0) ? g_xout[((long)b * 256 + sr) * DC + d] : 0.f;
}

// ---------------- launch ----------------
extern "C" void kernel_launch(void* const* d_in, const int* in_sizes, int n_in,
                              void* d_out, int out_size) {
    (void)in_sizes; (void)n_in; (void)out_size;
    const int*   value    = (const int*)d_in[0];
    const int*   depth    = (const int*)d_in[1];
    const int*   position = (const int*)d_in[2];
    const float* emb_val  = (const float*)d_in[3];
    const float* emb_dep  = (const float*)d_in[4];
    const float* emb_pos  = (const float*)d_in[5];
    const float* W0 = (const float*)d_in[6];
    const float* b0 = (const float*)d_in[7];
    const float* W1 = (const float*)d_in[8];
    const float* b1 = (const float*)d_in[9];
    const float* W2 = (const float*)d_in[10];
    const float* b2 = (const float*)d_in[11];
    float* out = (float*)d_out;

    __nv_bfloat16 *w0h, *w0l, *w1h, *w1l, *w2h, *w2l, *ehi, *elo;
    __nv_bfloat16 *x1h, *x1l, *x2h, *x2l;
    float *y0, *y1, *xo;
    cudaGetSymbolAddress((void**)&w0h, g_W0hi); cudaGetSymbolAddress((void**)&w0l, g_W0lo);
    cudaGetSymbolAddress((void**)&w1h, g_W1hi); cudaGetSymbolAddress((void**)&w1l, g_W1lo);
    cudaGetSymbolAddress((void**)&w2h, g_W2hi); cudaGetSymbolAddress((void**)&w2l, g_W2lo);
    cudaGetSymbolAddress((void**)&ehi, g_Ehi);  cudaGetSymbolAddress((void**)&elo, g_Elo);
    cudaGetSymbolAddress((void**)&x1h, g_x1hi); cudaGetSymbolAddress((void**)&x1l, g_x1lo);
    cudaGetSymbolAddress((void**)&x2h, g_x2hi); cudaGetSymbolAddress((void**)&x2l, g_x2lo);
    cudaGetSymbolAddress((void**)&y0, g_y0);    cudaGetSymbolAddress((void**)&y1, g_y1);
    cudaGetSymbolAddress((void**)&xo, g_xout);

    const int SMEM0 = 2 * (2 * 128 * 128 + 2 * 256 * 128);  // 196608 (BM=128,BN=256,2 stages)
    const int SMEM1 = 3 * (2 * 64 * 128 + 2 * 64 * 128);    // 98304  (64x64, 3 stages)
    cudaFuncSetAttribute(k_gemm<128, 256, 2048, 2>, cudaFuncAttributeMaxDynamicSharedMemorySize, SMEM0);
    cudaFuncSetAttribute(k_gemm<64, 64, 2048, 3>,   cudaFuncAttributeMaxDynamicSharedMemorySize, SMEM1);
    cudaFuncSetAttribute(k_gemm<64, 64, 1024, 3>,   cudaFuncAttributeMaxDynamicSharedMemorySize, SMEM1);

    k_wsplit<<<(256 * 8 * 256 + 255) / 256, 256>>>(W0, w0h, w0l, 8);
    k_wsplit<<<(256 * 8 * 256 + 255) / 256, 256>>>(W1, w1h, w1l, 8);
    k_wsplit<<<(256 * 4 * 256 + 255) / 256, 256>>>(W2, w2h, w2l, 4);
    k_indices<<<dim3(BB, 3), 1024>>>(value);
    k_embed<<<dim3(SC, BB), 256>>>(value, depth, position, emb_val, emb_dep, emb_pos);

    // GEMM0: 8192 x 2048 x 256 per batch — 64x1x2 = 128 CTAs = 1 wave
    k_gemm<128, 256, 2048, 2><<<dim3(64, 1, BB), 256, SMEM0>>>(
        ehi + (long)(L2C + L1C) * DC, elo + (long)(L2C + L1C) * DC, (long)SC * DC,
        w0h, w0l, b0, y0, (long)L1C * DC);
    k_gather_x1<<<dim3(L1C, BB), 256>>>();
    // GEMM1: 1024 x 2048 x 256 per batch
    k_gemm<64, 64, 2048, 3><<<dim3(16, 4, BB), 256, SMEM1>>>(
        x1h, x1l, (long)L1C * DC, w1h, w1l, b1, y1, (long)1024 * DC);
    k_gather_x2<<<dim3(L2C, BB), 256>>>();
    // GEMM2: 256 x 1024 x 256 per batch
    k_gemm<64, 64, 1024, 3><<<dim3(4, 4, BB), 256, SMEM1>>>(
        x2h, x2l, (long)L2C * DC, w2h, w2l, b2, xo, (long)256 * DC);
    k_output<<<dim3(256, BB), 256>>>(out);
}

// round 7
// speedup vs baseline: 4.0071x; 1.4272x over previous
#include <cuda_runtime.h>
#include <cuda_fp16.h>
#include <cstdint>

// ---------------- problem constants ----------------
#define BB   2
#define L2C  1024
#define L1C  8192
#define L0C  65536
#define SC   (L2C + L1C + L0C)   // 74752
#define DC   256

// ---------------- scratch (__device__ globals) ----------------
__device__ __half g_Ehi[(long)BB * SC * DC];
__device__ __half g_Elo[(long)BB * SC * DC];
__device__ __half g_W0[256 * 2048];
__device__ __half g_W1[256 * 2048];
__device__ __half g_W2[256 * 1024];
__device__ float g_y0[(long)BB * L1C * DC];
__device__ __half g_x1hi[BB * L1C * DC], g_x1lo[BB * L1C * DC];
__device__ float g_y1[BB * 1024 * DC];
__device__ __half g_x2hi[BB * L2C * DC], g_x2lo[BB * L2C * DC];
__device__ float g_xout[BB * 256 * DC];
__device__ int g_srcrow1[BB * L1C];
__device__ int g_srcrow2[BB * L2C];
__device__ int g_outrow[BB * 256];

// ---------------- helpers ----------------
__device__ __forceinline__ uint32_t smem_u32(const void* p) {
    uint32_t a;
    asm("{ .reg .u64 t; cvta.to.shared.u64 t, %1; cvt.u32.u64 %0, t; }" : "=r"(a) : "l"(p));
    return a;
}

__device__ __forceinline__ void split2h(float x, __half& h, __half& l) {
    h = __float2half(x);
    l = __float2half(x - __half2float(h));
}

__device__ __forceinline__ void cpasync16(uint32_t saddr, const void* gaddr) {
    asm volatile("cp.async.cg.shared.global [%0], [%1], 16;" :: "r"(saddr), "l"(gaddr));
}

__device__ __forceinline__ void ldsm4(uint32_t* r, uint32_t a) {
    asm volatile("ldmatrix.sync.aligned.m8n8.x4.shared.b16 {%0,%1,%2,%3}, [%4];"
                 : "=r"(r[0]), "=r"(r[1]), "=r"(r[2]), "=r"(r[3]) : "r"(a));
}

__device__ __forceinline__ void mma16816(float* d, const uint32_t* a, const uint32_t* b) {
    asm volatile(
        "mma.sync.aligned.m16n8k16.row.col.f32.f16.f16.f32 "
        "{%0,%1,%2,%3}, {%4,%5,%6,%7}, {%8,%9}, {%0,%1,%2,%3};"
        : "+f"(d[0]), "+f"(d[1]), "+f"(d[2]), "+f"(d[3])
        : "r"(a[0]), "r"(a[1]), "r"(a[2]), "r"(a[3]), "r"(b[0]), "r"(b[1]));
}

// ---------------- warp-shuffle exclusive scan over 1024 threads ----------------
__device__ __forceinline__ int exscan1024(int v, int tid, int* sW, int* total) {
    int lane = tid & 31, w = tid >> 5;
    int x = v;
    #pragma unroll
    for (int o = 1; o < 32; o <<= 1) {
        int t = __shfl_up_sync(0xFFFFFFFFu, x, o);
        if (lane >= o) x += t;
    }
    if (lane == 31) sW[w] = x;
    __syncthreads();
    if (tid < 32) {
        int y = sW[lane];
        #pragma unroll
        for (int o = 1; o < 32; o <<= 1) {
            int t = __shfl_up_sync(0xFFFFFFFFu, y, o);
            if (lane >= o) y += t;
        }
        sW[lane] = y;
    }
    __syncthreads();
    int off = (w == 0) ? 0 : sW[w - 1];
    int tot = sW[31];
    __syncthreads();
    *total = tot;
    return off + x - v;
}

// ---------------- index precomputation: grid (B, 3), 1024 threads ----------------
__global__ void __launch_bounds__(1024) k_indices(const int* __restrict__ value) {
    __shared__ int sOrder[8192];
    __shared__ int sScan[32];
    int b = blockIdx.x, sec = blockIdx.y, tid = threadIdx.x;
    const int* vb = value + (long)b * SC;

    if (sec == 0) {
        int base = tid * 8, local = 0;
        unsigned mask = 0;
        #pragma unroll
        for (int i = 0; i < 8; i++) {
            int p = (vb[L2C + L1C + (base + i) * 8] != 0);
            mask |= (unsigned)p << i; local += p;
        }
        int tot; int ex = exscan1024(local, tid, sScan, &tot);
        int rt = ex, rf = base - ex;
        #pragma unroll
        for (int i = 0; i < 8; i++) {
            int j = base + i;
            if ((mask >> i) & 1u) sOrder[rt++] = j;
            else                  sOrder[tot + rf++] = j;
        }
        __syncthreads();
        local = 0; mask = 0;
        #pragma unroll
        for (int i = 0; i < 8; i++) {
            int p = (vb[L2C + base + i] == 2);
            mask |= (unsigned)p << i; local += p;
        }
        ex = exscan1024(local, tid, sScan, &tot);
        int r = ex;
        #pragma unroll
        for (int i = 0; i < 8; i++) {
            int j = base + i; int sr = -1;
            if ((mask >> i) & 1u) { sr = sOrder[min(r, 8191)]; r++; }
            g_srcrow1[b * L1C + j] = sr;
        }
    } else if (sec == 1) {
        int p = (vb[L2C + tid * 8] != 0);
        int tot; int ex = exscan1024(p, tid, sScan, &tot);
        if (p) sOrder[ex] = tid;
        else   sOrder[tot + tid - ex] = tid;
        __syncthreads();
        int q = (vb[tid] == 2);
        int ex2 = exscan1024(q, tid, sScan, &tot);
        g_srcrow2[b * L2C + tid] = q ? sOrder[min(ex2, 1023)] : -1;
    } else {
        int any = 0;
        #pragma unroll
        for (int t = 0; t < 8; t++) any |= (vb[L2C + tid * 8 + t] == 2);
        sOrder[tid] = any;
        __syncthreads();
        int p = (vb[tid] == 2);
        int tot; int ex = exscan1024(p, tid, sScan, &tot);
        int m2 = p ? sOrder[min(ex, 1023)] : 0;
        sOrder[2048 + tid] = m2;
        __syncthreads();
        int m2g = 0;
        if (tid < 256)
            m2g = sOrder[2048 + 4 * tid] | sOrder[2048 + 4 * tid + 1]
                | sOrder[2048 + 4 * tid + 2] | sOrder[2048 + 4 * tid + 3];
        int ex2 = exscan1024((tid < 256 && m2g) ? 1 : 0, tid, sScan, &tot);
        if (tid < 256) sOrder[4096 + tid] = -1;
        __syncthreads();
        if (tid < 256 && m2g) sOrder[4096 + ex2] = tid;
        __syncthreads();
        if (tid < 256) g_outrow[b * 256 + tid] = sOrder[4096 + tid];
    }
}

// ---------------- embedding -> hi/lo fp16, half2 stores ----------------
__global__ void k_embed(const int* __restrict__ value, const int* __restrict__ depth,
                        const int* __restrict__ position,
                        const float* __restrict__ emb_val, const float* __restrict__ emb_dep,
                        const float* __restrict__ emb_pos) {
    int s = blockIdx.x, b = blockIdx.y;
    int d = threadIdx.x * 2;
    long row = (long)b * SC + s;
    int v = value[row], dep = depth[row];
    const int* p = position + row * 3;
    float2 e = *(const float2*)&emb_val[v * DC + d];
    float2 t;
    t = *(const float2*)&emb_dep[dep * DC + d];                 e.x += t.x; e.y += t.y;
    t = *(const float2*)&emb_pos[(0 * 33 + p[0]) * DC + d];     e.x += t.x; e.y += t.y;
    t = *(const float2*)&emb_pos[(1 * 33 + p[1]) * DC + d];     e.x += t.x; e.y += t.y;
    t = *(const float2*)&emb_pos[(2 * 33 + p[2]) * DC + d];     e.x += t.x; e.y += t.y;
    __half h0, l0, h1, l1;
    split2h(e.x, h0, l0); split2h(e.y, h1, l1);
    *(__half2*)&g_Ehi[row * DC + d] = __halves2half2(h0, h1);
    *(__half2*)&g_Elo[row * DC + d] = __halves2half2(l0, l1);
}

// ---------------- merged weight convert: Wh[o][t*256+d] = fp16(W[o,d,t]) ----------------
__global__ void k_wsplit_all(const float* __restrict__ W0, const float* __restrict__ W1,
                             const float* __restrict__ W2) {
    int idx = blockIdx.x * blockDim.x + threadIdx.x;
    const float* W; __half* O; int sK;
    if (idx < 524288)        { W = W0; O = g_W0; sK = 8; }
    else if (idx < 1048576)  { idx -= 524288;  W = W1; O = g_W1; sK = 8; }
    else if (idx < 1310720)  { idx -= 1048576; W = W2; O = g_W2; sK = 4; }
    else return;
    int d = idx & 255;
    int rem = idx >> 8;
    int t = rem % sK;
    int o = rem / sK;
    O[o * (sK * 256) + t * 256 + d] = __float2half(W[(o * 256 + d) * sK + t]);
}

// ---------------- 2-term fp16 split GEMM via mma.sync ----------------
// C[M x 256] = (Ah+Al)[M x KK] @ Bh^T + bias, fp32 accumulate.
// 256 threads / 8 warps (2x4). BK=64 fp16 (128B SW128 rows). STAGES-deep cp.async.
template <int BM, int BN, int KK, int STAGES>
__global__ void __launch_bounds__(256, 1) k_gemm(
    const __half* __restrict__ Ahi, const __half* __restrict__ Alo, long strideA,
    const __half* __restrict__ Bh,
    const float* __restrict__ bias, float* __restrict__ C, long strideC)
{
    constexpr int NC = KK / 64;
    constexpr int ABYTES = BM * 128;
    constexpr int BBYTES = BN * 128;
    constexpr int STAGE = 2 * ABYTES + BBYTES;
    constexpr int WM = BM / 2, WN = BN / 4;
    constexpr int MT = WM / 16, NP = WN / 16;
    constexpr int TOTROWS = 2 * BM + BN;

    extern __shared__ __align__(1024) char smem[];
    uint32_t sb = smem_u32(smem);

    int tid = threadIdx.x;
    int lane = tid & 31, wid = tid >> 5;
    int wm0 = (wid >> 2) * WM;
    int wn0 = (wid & 3) * WN;
    int m0 = blockIdx.x * BM;
    int n0 = blockIdx.y * BN;
    int b = blockIdx.z;

    const __half* Ah = Ahi + (long)b * strideA;
    const __half* Al = Alo + (long)b * strideA;
    float* Cb = C + (long)b * strideC;

    float acc[MT][2 * NP][4];
    #pragma unroll
    for (int i = 0; i < MT; i++)
        #pragma unroll
        for (int j = 0; j < 2 * NP; j++)
            #pragma unroll
            for (int k = 0; k < 4; k++) acc[i][j][k] = 0.f;

    auto load_chunk = [&](int c) {
        uint32_t st = sb + (uint32_t)((c % STAGES) * STAGE);
        long k0 = (long)c * 64;
        #pragma unroll
        for (int i = tid; i < TOTROWS * 8; i += 256) {
            int r = i >> 3, seg = i & 7;
            const __half* g;
            uint32_t base;
            if (r < BM)          { g = Ah + (long)(m0 + r) * KK;                  base = st; }
            else if (r < 2 * BM) { int rr = r - BM;     g = Al + (long)(m0 + rr) * KK; base = st + ABYTES;     r = rr; }
            else                 { int rr = r - 2 * BM; g = Bh + (long)(n0 + rr) * KK; base = st + 2 * ABYTES; r = rr; }
            uint32_t off = (uint32_t)(r * 128 + seg * 16);
            uint32_t dst = base + (off ^ (uint32_t)((r & 7) << 4));
            cpasync16(dst, g + k0 + seg * 8);
        }
        asm volatile("cp.async.commit_group;" ::: "memory");
    };

    load_chunk(0);
    if (NC > 1) load_chunk(1);

    const uint32_t xorm = (uint32_t)((lane & 7) << 4);
    const uint32_t a_lrow = (uint32_t)(lane & 15);
    const uint32_t a_khalf = (uint32_t)(lane & 16);
    const uint32_t b_lrow = (uint32_t)((lane & 7) | ((lane & 16) >> 1));
    const uint32_t b_khalf = (uint32_t)((lane & 8) << 1);

    for (int c = 0; c < NC; ++c) {
        if (c + 2 < NC) {
            load_chunk(c + 2);
            asm volatile("cp.async.wait_group 2;" ::: "memory");
        } else if (c + 1 < NC) {
            asm volatile("cp.async.wait_group 1;" ::: "memory");
        } else {
            asm volatile("cp.async.wait_group 0;" ::: "memory");
        }
        __syncthreads();

        uint32_t st = sb + (uint32_t)((c % STAGES) * STAGE);
        #pragma unroll
        for (int ks = 0; ks < 4; ks++) {
            uint32_t a[2][MT][4], bf[NP][4];
            #pragma unroll
            for (int mi = 0; mi < MT; mi++) {
                uint32_t off = (uint32_t)((wm0 + mi * 16 + a_lrow) * 128) + (uint32_t)(ks * 32) + a_khalf;
                ldsm4(a[0][mi], st + (off ^ xorm));
                ldsm4(a[1][mi], st + ABYTES + (off ^ xorm));
            }
            #pragma unroll
            for (int pi = 0; pi < NP; pi++) {
                uint32_t off = (uint32_t)((wn0 + pi * 16 + b_lrow) * 128) + (uint32_t)(ks * 32) + b_khalf;
                ldsm4(bf[pi], st + 2 * ABYTES + (off ^ xorm));
            }
            #pragma unroll
            for (int mi = 0; mi < MT; mi++)
                #pragma unroll
                for (int pi = 0; pi < NP; pi++) {
                    mma16816(acc[mi][2 * pi],     a[0][mi], &bf[pi][0]);   // hi * B
                    mma16816(acc[mi][2 * pi + 1], a[0][mi], &bf[pi][2]);
                    mma16816(acc[mi][2 * pi],     a[1][mi], &bf[pi][0]);   // lo * B
                    mma16816(acc[mi][2 * pi + 1], a[1][mi], &bf[pi][2]);
                }
        }
        __syncthreads();
    }

    // epilogue
    int g4 = lane >> 2, t4 = lane & 3;
    #pragma unroll
    for (int mi = 0; mi < MT; mi++) {
        #pragma unroll
        for (int ni = 0; ni < 2 * NP; ni++) {
            int m = m0 + wm0 + mi * 16 + g4;
            int col = n0 + wn0 + ni * 8 + t4 * 2;
            float bx = bias[col], by = bias[col + 1];
            float2 v0 = make_float2(acc[mi][ni][0] + bx, acc[mi][ni][1] + by);
            float2 v1 = make_float2(acc[mi][ni][2] + bx, acc[mi][ni][3] + by);
            *(float2*)&Cb[(long)m * 256 + col] = v0;
            *(float2*)&Cb[(long)(m + 8) * 256 + col] = v1;
        }
    }
}

// ---------------- substitution gathers -> hi/lo fp16 (half2) ----------------
__global__ void k_gather_x1() {
    int l = blockIdx.x, b = blockIdx.y;
    int d = threadIdx.x * 2;
    int sr = g_srcrow1[b * L1C + l];
    long dst = ((long)b * L1C + l) * DC + d;
    if (sr >= 0) {
        float2 v = *(const float2*)&g_y0[((long)b * L1C + sr) * DC + d];
        __half h0, l0, h1, l1;
        split2h(v.x, h0, l0); split2h(v.y, h1, l1);
        *(__half2*)&g_x1hi[dst] = __halves2half2(h0, h1);
        *(__half2*)&g_x1lo[dst] = __halves2half2(l0, l1);
    } else {
        long src = ((long)b * SC + L2C + l) * DC + d;
        *(__half2*)&g_x1hi[dst] = *(const __half2*)&g_Ehi[src];
        *(__half2*)&g_x1lo[dst] = *(const __half2*)&g_Elo[src];
    }
}

__global__ void k_gather_x2() {
    int l = blockIdx.x, b = blockIdx.y;
    int d = threadIdx.x * 2;
    int sr = g_srcrow2[b * L2C + l];
    long dst = ((long)b * L2C + l) * DC + d;
    if (sr >= 0) {
        float2 v = *(const float2*)&g_y1[((long)b * 1024 + sr) * DC + d];
        __half h0, l0, h1, l1;
        split2h(v.x, h0, l0); split2h(v.y, h1, l1);
        *(__half2*)&g_x2hi[dst] = __halves2half2(h0, h1);
        *(__half2*)&g_x2lo[dst] = __halves2half2(l0, l1);
    } else {
        long src = ((long)b * SC + l) * DC + d;
        *(__half2*)&g_x2hi[dst] = *(const __half2*)&g_Ehi[src];
        *(__half2*)&g_x2lo[dst] = *(const __half2*)&g_Elo[src];
    }
}

// ---------------- final compaction + zero fill ----------------
__global__ void k_output(float* __restrict__ out) {
    int g = blockIdx.x, b = blockIdx.y, d = threadIdx.x;
    int sr = g_outrow[b * 256 + g];
    out[((long)b * 256 + g) * DC + d] = (sr >= 0) ? g_xout[((long)b * 256 + sr) * DC + d] : 0.f;
}

// ---------------- launch ----------------
extern "C" void kernel_launch(void* const* d_in, const int* in_sizes, int n_in,
                              void* d_out, int out_size) {
    (void)in_sizes; (void)n_in; (void)out_size;
    const int*   value    = (const int*)d_in[0];
    const int*   depth    = (const int*)d_in[1];
    const int*   position = (const int*)d_in[2];
    const float* emb_val  = (const float*)d_in[3];
    const float* emb_dep  = (const float*)d_in[4];
    const float* emb_pos  = (const float*)d_in[5];
    const float* W0 = (const float*)d_in[6];
    const float* b0 = (const float*)d_in[7];
    const float* W1 = (const float*)d_in[8];
    const float* b1 = (const float*)d_in[9];
    const float* W2 = (const float*)d_in[10];
    const float* b2 = (const float*)d_in[11];
    float* out = (float*)d_out;

    __half *w0, *w1, *w2, *ehi, *elo, *x1h, *x1l, *x2h, *x2l;
    float *y0, *y1, *xo;
    cudaGetSymbolAddress((void**)&w0, g_W0);
    cudaGetSymbolAddress((void**)&w1, g_W1);
    cudaGetSymbolAddress((void**)&w2, g_W2);
    cudaGetSymbolAddress((void**)&ehi, g_Ehi);  cudaGetSymbolAddress((void**)&elo, g_Elo);
    cudaGetSymbolAddress((void**)&x1h, g_x1hi); cudaGetSymbolAddress((void**)&x1l, g_x1lo);
    cudaGetSymbolAddress((void**)&x2h, g_x2hi); cudaGetSymbolAddress((void**)&x2l, g_x2lo);
    cudaGetSymbolAddress((void**)&y0, g_y0);    cudaGetSymbolAddress((void**)&y1, g_y1);
    cudaGetSymbolAddress((void**)&xo, g_xout);

    const int SMEM0 = 3 * (2 * 128 * 128 + 256 * 128);  // 196608 (BM128,BN256, 3 stages)
    const int SMEM1 = 4 * (2 * 64 * 128 + 64 * 128);    // 98304  (64x64, 4 stages)
    cudaFuncSetAttribute(k_gemm<128, 256, 2048, 3>, cudaFuncAttributeMaxDynamicSharedMemorySize, SMEM0);
    cudaFuncSetAttribute(k_gemm<64, 64, 2048, 4>,   cudaFuncAttributeMaxDynamicSharedMemorySize, SMEM1);
    cudaFuncSetAttribute(k_gemm<64, 64, 1024, 4>,   cudaFuncAttributeMaxDynamicSharedMemorySize, SMEM1);

    k_wsplit_all<<<(1310720 + 255) / 256, 256>>>(W0, W1, W2);
    k_embed<<<dim3(SC, BB), 128>>>(value, depth, position, emb_val, emb_dep, emb_pos);
    k_indices<<<dim3(BB, 3), 1024>>>(value);

    // GEMM0: 8192 x 2048 x 256 per batch — 64x1x2 = 128 CTAs = 1 wave
    k_gemm<128, 256, 2048, 3><<<dim3(64, 1, BB), 256, SMEM0>>>(
        ehi + (long)(L2C + L1C) * DC, elo + (long)(L2C + L1C) * DC, (long)SC * DC,
        w0, b0, y0, (long)L1C * DC);
    k_gather_x1<<<dim3(L1C, BB), 128>>>();
    // GEMM1: 1024 x 2048 x 256 per batch
    k_gemm<64, 64, 2048, 4><<<dim3(16, 4, BB), 256, SMEM1>>>(
        x1h, x1l, (long)L1C * DC, w1, b1, y1, (long)1024 * DC);
    k_gather_x2<<<dim3(L2C, BB), 128>>>();
    // GEMM2: 256 x 1024 x 256 per batch
    k_gemm<64, 64, 1024, 4><<<dim3(4, 4, BB), 256, SMEM1>>>(
        x2h, x2l, (long)L2C * DC, w2, b2, xo, (long)256 * DC);
    k_output<<<dim3(256, BB), 256>>>(out);
}